// round 2
// baseline (speedup 1.0000x reference)
#include <cuda_runtime.h>
#include <math.h>
#include <float.h>

#define BB 16
#define LL 4096
#define NN 512
#define DD 256
#define TL 32
#define TN 32
#define EPSV 1e-8f

#define XS_STRIDE 260
#define PS_STRIDE 260
#define SS_STRIDE 516

// float offsets into dynamic smem
#define XS_OFF 0
#define PS_OFF (TL * XS_STRIDE)                    // 8320
#define SIM_OFF (PS_OFF + TN * PS_STRIDE)          // 16640
#define XN_OFF (SIM_OFF + TL * SS_STRIDE)          // 33152
#define PN_OFF (XN_OFF + TL)                       // 33184
#define SMEM_FLOATS (PN_OFF + NN)                  // 33696
#define SMEM_BYTES (SMEM_FLOATS * 4)               // 134784

__device__ float g_pnorm[BB * NN];

__global__ void pnorm_kernel(const float* __restrict__ profile) {
    int w = (blockIdx.x * blockDim.x + threadIdx.x) >> 5;
    int lane = threadIdx.x & 31;
    if (w >= BB * NN) return;
    const float* p = profile + (size_t)w * DD;
    float s = 0.f;
#pragma unroll
    for (int i = lane; i < DD; i += 32) {
        float v = p[i];
        s += v * v;
    }
#pragma unroll
    for (int o = 16; o > 0; o >>= 1) s += __shfl_xor_sync(0xffffffffu, s, o);
    if (lane == 0) g_pnorm[w] = sqrtf(s);
}

__global__ __launch_bounds__(256, 1) void cosattn_fused_kernel(
    const float* __restrict__ x,       // (B,L,D)
    const float* __restrict__ prof,    // (B,N,D)
    const int* __restrict__ lens,      // (B,)
    float* __restrict__ emb,           // (B,L,D)
    float* __restrict__ wout           // (B,L,N)
) {
    extern __shared__ float smem[];
    float* xs = smem + XS_OFF;
    float* ps = smem + PS_OFF;
    float* sims = smem + SIM_OFF;
    float* xn = smem + XN_OFF;
    float* pn = smem + PN_OFF;

    int b = blockIdx.x >> 7;      // / (LL/TL = 128)
    int lt = blockIdx.x & 127;
    int l0 = lt * TL;
    int tid = threadIdx.x;

    // ---- load X tile (32 x 256) as float4, coalesced ----
    const float* xg = x + ((size_t)b * LL + l0) * DD;
    for (int i = tid; i < TL * DD / 4; i += 256) {
        int r = i >> 6;        // D/4 = 64 float4 per row
        int c = i & 63;
        float4 v = ((const float4*)(xg + (size_t)r * DD))[c];
        *((float4*)&xs[r * XS_STRIDE + c * 4]) = v;
    }
    // ---- load profile norms for this batch ----
    for (int i = tid; i < NN; i += 256) pn[i] = g_pnorm[b * NN + i];
    int plen = lens[b];
    __syncthreads();

    // ---- x-norms: warp per 4 rows ----
    {
        int w = tid >> 5, lane = tid & 31;
#pragma unroll
        for (int rr = 0; rr < 4; rr++) {
            int r = w * 4 + rr;
            float s = 0.f;
#pragma unroll
            for (int i = lane; i < DD; i += 32) {
                float v = xs[r * XS_STRIDE + i];
                s += v * v;
            }
#pragma unroll
            for (int o = 16; o > 0; o >>= 1) s += __shfl_xor_sync(0xffffffffu, s, o);
            if (lane == 0) xn[r] = sqrtf(s);
        }
    }
    __syncthreads();

    // ---- GEMM1: sims[l][n] = x[l]·p[n] scaled + masked, over 16 n-tiles ----
    int tx = tid & 15, ty = tid >> 4;
    for (int nt = 0; nt < NN / TN; nt++) {
        int n0 = nt * TN;
        const float* pg = prof + ((size_t)b * NN + n0) * DD;
        for (int i = tid; i < TN * DD / 4; i += 256) {
            int r = i >> 6;
            int c = i & 63;
            float4 v = ((const float4*)(pg + (size_t)r * DD))[c];
            *((float4*)&ps[r * PS_STRIDE + c * 4]) = v;
        }
        __syncthreads();

        float a00 = 0.f, a01 = 0.f, a10 = 0.f, a11 = 0.f;
        const float4* xa0 = (const float4*)&xs[ty * XS_STRIDE];
        const float4* xa1 = (const float4*)&xs[(ty + 16) * XS_STRIDE];
        const float4* pb0 = (const float4*)&ps[tx * PS_STRIDE];
        const float4* pb1 = (const float4*)&ps[(tx + 16) * PS_STRIDE];
#pragma unroll 8
        for (int k = 0; k < DD / 4; k++) {
            float4 a0 = xa0[k], a1 = xa1[k], b0 = pb0[k], b1 = pb1[k];
            a00 += a0.x * b0.x + a0.y * b0.y + a0.z * b0.z + a0.w * b0.w;
            a01 += a0.x * b1.x + a0.y * b1.y + a0.z * b1.z + a0.w * b1.w;
            a10 += a1.x * b0.x + a1.y * b0.y + a1.z * b0.z + a1.w * b0.w;
            a11 += a1.x * b1.x + a1.y * b1.y + a1.z * b1.z + a1.w * b1.w;
        }

        int li0 = ty, li1 = ty + 16;
        int ni0 = n0 + tx, ni1 = n0 + tx + 16;
        float xl0 = xn[li0], xl1 = xn[li1];
        float pn0 = pn[ni0], pn1 = pn[ni1];

        float s00 = a00 / fmaxf(xl0 * pn0, EPSV);
        float s01 = a01 / fmaxf(xl0 * pn1, EPSV);
        float s10 = a10 / fmaxf(xl1 * pn0, EPSV);
        float s11 = a11 / fmaxf(xl1 * pn1, EPSV);
        if (ni0 >= plen) { s00 = -FLT_MAX; s10 = -FLT_MAX; }
        if (ni1 >= plen) { s01 = -FLT_MAX; s11 = -FLT_MAX; }
        sims[li0 * SS_STRIDE + ni0] = s00;
        sims[li0 * SS_STRIDE + ni1] = s01;
        sims[li1 * SS_STRIDE + ni0] = s10;
        sims[li1 * SS_STRIDE + ni1] = s11;
        __syncthreads();
    }

    // ---- softmax over N per row, warp per 4 rows; write weights ----
    {
        int w = tid >> 5, lane = tid & 31;
        float* wg = wout + ((size_t)b * LL + l0) * NN;
#pragma unroll
        for (int rr = 0; rr < 4; rr++) {
            int r = w * 4 + rr;
            float* row = &sims[r * SS_STRIDE];
            float m = -FLT_MAX;
#pragma unroll
            for (int i = lane; i < NN; i += 32) m = fmaxf(m, row[i]);
#pragma unroll
            for (int o = 16; o > 0; o >>= 1) m = fmaxf(m, __shfl_xor_sync(0xffffffffu, m, o));
            float sum = 0.f;
#pragma unroll
            for (int i = lane; i < NN; i += 32) {
                float e = __expf(row[i] - m);
                row[i] = e;
                sum += e;
            }
#pragma unroll
            for (int o = 16; o > 0; o >>= 1) sum += __shfl_xor_sync(0xffffffffu, sum, o);
            float inv = 1.0f / sum;
#pragma unroll
            for (int i = lane; i < NN; i += 32) {
                float wv = row[i] * inv;
                row[i] = wv;
                wg[(size_t)r * NN + i] = wv;
            }
        }
    }
    __syncthreads();

    // ---- GEMM2: emb[l][d] = sum_n w[l][n] * P[n][d]; thread owns one d ----
    int d = tid;
    float acc[TL];
#pragma unroll
    for (int l = 0; l < TL; l++) acc[l] = 0.f;

    for (int nt = 0; nt < NN / TN; nt++) {
        int n0 = nt * TN;
        const float* pg = prof + ((size_t)b * NN + n0) * DD;
        for (int i = tid; i < TN * DD / 4; i += 256) {
            int r = i >> 6;
            int c = i & 63;
            float4 v = ((const float4*)(pg + (size_t)r * DD))[c];
            *((float4*)&ps[r * PS_STRIDE + c * 4]) = v;
        }
        __syncthreads();

#pragma unroll
        for (int nn = 0; nn < TN; nn += 4) {
            float p0 = ps[(nn + 0) * PS_STRIDE + d];
            float p1 = ps[(nn + 1) * PS_STRIDE + d];
            float p2 = ps[(nn + 2) * PS_STRIDE + d];
            float p3 = ps[(nn + 3) * PS_STRIDE + d];
#pragma unroll
            for (int l = 0; l < TL; l++) {
                float4 wv = *(const float4*)&sims[l * SS_STRIDE + n0 + nn];
                acc[l] += wv.x * p0 + wv.y * p1 + wv.z * p2 + wv.w * p3;
            }
        }
        __syncthreads();
    }

    float* eg = emb + ((size_t)b * LL + l0) * DD + d;
#pragma unroll
    for (int l = 0; l < TL; l++) eg[(size_t)l * DD] = acc[l];
}

extern "C" void kernel_launch(void* const* d_in, const int* in_sizes, int n_in,
                              void* d_out, int out_size) {
    const float* x = (const float*)d_in[0];     // spk_decoder_out (B,L,D)
    const float* prof = (const float*)d_in[1];  // profile (B,N,D)
    const int* lens = (const int*)d_in[2];      // profile_lens (B,)

    float* emb = (float*)d_out;                          // (B,L,D)
    float* wout = (float*)d_out + (size_t)BB * LL * DD;  // (B,L,N)

    static bool attr_set = false;
    // setting an attribute is idempotent and not a stream op; do it every call
    cudaFuncSetAttribute(cosattn_fused_kernel,
                         cudaFuncAttributeMaxDynamicSharedMemorySize, SMEM_BYTES);
    (void)attr_set;

    // profile norms: one warp per (b,n); 8 warps per block
    pnorm_kernel<<<(BB * NN) / 8, 256>>>(prof);

    // fused attention: one block per (b, 32-row L tile)
    cosattn_fused_kernel<<<BB * (LL / TL), 256, SMEM_BYTES>>>(x, prof, lens, emb, wout);
}

// round 5
// speedup vs baseline: 1.7523x; 1.7523x over previous
#include <cuda_runtime.h>
#include <math.h>
#include <float.h>

#define BB 16
#define LL 4096
#define NN 512
#define DD 256
#define EPSV 1e-8f

// ---------------- Kernel A layout ----------------
#define A_TL 64
#define A_NC 256
#define A_KC 32
#define XS_STRIDE 260
#define PS_STRIDE 260
#define A_XS_OFF 0
#define A_PS_OFF (A_TL * XS_STRIDE)              // 16640
#define A_PN_OFF (A_PS_OFF + A_KC * PS_STRIDE)   // 24960
#define A_XN_OFF (A_PN_OFF + NN)                 // 25472
#define A_RS_OFF (A_XN_OFF + A_TL)               // 25536
#define A_SMEM_FLOATS (A_RS_OFF + A_TL)          // 25600
#define A_SMEM_BYTES (A_SMEM_FLOATS * 4)         // 102400

// ---------------- Kernel B layout ----------------
#define B_TL 64
#define B_NC 64
#define ES_STRIDE 68
#define PB_STRIDE 260
#define B_ES_OFF 0
#define B_PS_OFF (B_TL * ES_STRIDE)              // 4352
#define B_IV_OFF (B_PS_OFF + B_NC * PB_STRIDE)   // 20992
#define B_SMEM_FLOATS (B_IV_OFF + B_TL)          // 21056
#define B_SMEM_BYTES (B_SMEM_FLOATS * 4)         // 84224

__device__ float g_pnorm[BB * NN];
__device__ float g_rsum[BB * LL];

// ---------------- profile norms ----------------
__global__ void pnorm_kernel(const float* __restrict__ profile) {
    int w = (blockIdx.x * blockDim.x + threadIdx.x) >> 5;
    int lane = threadIdx.x & 31;
    if (w >= BB * NN) return;
    const float* p = profile + (size_t)w * DD;
    float s = 0.f;
#pragma unroll
    for (int i = lane; i < DD; i += 32) {
        float v = p[i];
        s += v * v;
    }
#pragma unroll
    for (int o = 16; o > 0; o >>= 1) s += __shfl_xor_sync(0xffffffffu, s, o);
    if (lane == 0) g_pnorm[w] = sqrtf(s);
}

// ---------------- Kernel A: sims -> exp weights (unnormalized) + rowsums ----
__global__ __launch_bounds__(256, 2) void cosattn_sim_kernel(
    const float* __restrict__ x,     // (B,L,D)
    const float* __restrict__ prof,  // (B,N,D)
    const int* __restrict__ lens,
    float* __restrict__ wout         // (B,L,N) <- exp(sim) unnormalized
) {
    extern __shared__ float sm[];
    float* Xs = sm + A_XS_OFF;       // [64][260] row-major (l,k)
    float* Ps = sm + A_PS_OFF;       // [32][260] k-major (k,n)
    float* pns = sm + A_PN_OFF;      // [512]
    float* xn = sm + A_XN_OFF;       // [64]
    float* rsum = sm + A_RS_OFF;     // [64]

    int b = blockIdx.x >> 6;
    int lt = blockIdx.x & 63;
    int l0 = lt * A_TL;
    int tid = threadIdx.x;
    int ty = tid >> 5;       // 0..7 : L group (8 rows each)
    int tx = tid & 31;       // 0..31: N group (8 cols each)

    const float* xg = x + ((size_t)b * LL + l0) * DD;
    for (int idx = tid; idx < A_TL * DD / 4; idx += 256) {
        int row = idx >> 6;
        int c = idx & 63;
        float4 v = *(const float4*)(xg + (size_t)row * DD + c * 4);
        *(float4*)&Xs[row * XS_STRIDE + c * 4] = v;
    }
    for (int i = tid; i < NN; i += 256) pns[i] = g_pnorm[b * NN + i];
    if (tid < A_TL) rsum[tid] = 0.f;
    int plen = __ldg(&lens[b]);
    __syncthreads();

    // x row norms: warp ty owns rows ty*8..ty*8+7
#pragma unroll
    for (int rr = 0; rr < 8; rr++) {
        int r = ty * 8 + rr;
        float s = 0.f;
#pragma unroll
        for (int i = tx; i < DD; i += 32) {
            float v = Xs[r * XS_STRIDE + i];
            s += v * v;
        }
#pragma unroll
        for (int o = 16; o > 0; o >>= 1) s += __shfl_xor_sync(0xffffffffu, s, o);
        if (tx == 0) xn[r] = sqrtf(s);
    }

    for (int nch = 0; nch < NN / A_NC; nch++) {
        int n0 = nch * A_NC;
        float acc[64];
#pragma unroll
        for (int i = 0; i < 64; i++) acc[i] = 0.f;

        for (int kc = 0; kc < DD / A_KC; kc++) {
            int k0 = kc * A_KC;
            __syncthreads();
            // transpose-load P chunk -> Ps[k][n], k-major
#pragma unroll
            for (int s = 0; s < 8; s++) {
                int idx = s * 256 + tid;
                int n = idx & 255;
                int c = idx >> 8;
                float4 v = __ldg((const float4*)(prof +
                    ((size_t)b * NN + n0 + n) * DD + k0 + c * 4));
                Ps[(c * 4 + 0) * PS_STRIDE + n] = v.x;
                Ps[(c * 4 + 1) * PS_STRIDE + n] = v.y;
                Ps[(c * 4 + 2) * PS_STRIDE + n] = v.z;
                Ps[(c * 4 + 3) * PS_STRIDE + n] = v.w;
            }
            __syncthreads();

            // 64 FFMA per k; a-operands are warp-uniform scalar LDS (broadcast)
#pragma unroll
            for (int k = 0; k < A_KC; k++) {
                float4 b0 = *(const float4*)&Ps[k * PS_STRIDE + tx * 8];
                float4 b1 = *(const float4*)&Ps[k * PS_STRIDE + tx * 8 + 4];
                const float* xrow = &Xs[ty * 8 * XS_STRIDE + k0 + k];
#pragma unroll
                for (int i = 0; i < 8; i++) {
                    float av = xrow[i * XS_STRIDE];
                    acc[i * 8 + 0] += av * b0.x;
                    acc[i * 8 + 1] += av * b0.y;
                    acc[i * 8 + 2] += av * b0.z;
                    acc[i * 8 + 3] += av * b0.w;
                    acc[i * 8 + 4] += av * b1.x;
                    acc[i * 8 + 5] += av * b1.y;
                    acc[i * 8 + 6] += av * b1.z;
                    acc[i * 8 + 7] += av * b1.w;
                }
            }
        }

        // epilogue: scale, mask, exp, write, deterministic warp-reduced rowsum
#pragma unroll
        for (int i = 0; i < 8; i++) {
            int r = ty * 8 + i;
            float xr = xn[r];
            float e[8];
            float esum = 0.f;
#pragma unroll
            for (int j = 0; j < 8; j++) {
                int n = n0 + tx * 8 + j;
                float sim = acc[i * 8 + j] / fmaxf(xr * pns[n], EPSV);
                float ev = (n < plen) ? __expf(sim) : 0.f;
                e[j] = ev;
                esum += ev;
            }
#pragma unroll
            for (int o = 16; o > 0; o >>= 1)
                esum += __shfl_xor_sync(0xffffffffu, esum, o);
            if (tx == 0) rsum[r] += esum;
            float* dst = wout + ((size_t)b * LL + l0 + r) * NN + n0 + tx * 8;
            *(float4*)dst = make_float4(e[0], e[1], e[2], e[3]);
            *(float4*)(dst + 4) = make_float4(e[4], e[5], e[6], e[7]);
        }
    }
    __syncthreads();
    if (tid < A_TL) g_rsum[(size_t)b * LL + l0 + tid] = rsum[tid];
}

// ---------------- Kernel B: normalize weights + emb = W @ P ----------------
__global__ __launch_bounds__(256, 2) void cosattn_av_kernel(
    const float* __restrict__ prof,  // (B,N,D)
    float* __restrict__ wout,        // (B,L,N) in: exp, out: normalized
    float* __restrict__ emb          // (B,L,D)
) {
    extern __shared__ float sm[];
    float* Es = sm + B_ES_OFF;       // [64][68]  (l, n-chunk)
    float* Ps = sm + B_PS_OFF;       // [64][260] (n, d)
    float* inv = sm + B_IV_OFF;      // [64]

    int b = blockIdx.x >> 6;
    int lt = blockIdx.x & 63;
    int l0 = lt * B_TL;
    int tid = threadIdx.x;
    int ty = tid >> 5;       // 0..7 : L group
    int tx = tid & 31;       // 0..31: D group (8 cols each)

    if (tid < B_TL) inv[tid] = 1.0f / g_rsum[(size_t)b * LL + l0 + tid];

    float acc[64];
#pragma unroll
    for (int i = 0; i < 64; i++) acc[i] = 0.f;

    __syncthreads();

    for (int nc = 0; nc < NN / B_NC; nc++) {
        int n0 = nc * B_NC;
        __syncthreads();
        // load E tile 64x64, normalize, write back (coalesced), stage in smem
#pragma unroll
        for (int s = 0; s < 4; s++) {
            int idx = s * 256 + tid;
            int row = idx >> 4;
            int c = idx & 15;
            float* gp = wout + ((size_t)b * LL + l0 + row) * NN + n0 + c * 4;
            float4 v = *(float4*)gp;
            float iv = inv[row];
            v.x *= iv; v.y *= iv; v.z *= iv; v.w *= iv;
            *(float4*)gp = v;
            *(float4*)&Es[row * ES_STRIDE + c * 4] = v;
        }
        // load P chunk (64 n-rows x 256 d), coalesced
#pragma unroll
        for (int s = 0; s < 16; s++) {
            int idx = s * 256 + tid;
            int row = idx >> 6;
            int c = idx & 63;
            float4 v = __ldg((const float4*)(prof +
                ((size_t)b * NN + n0 + row) * DD + c * 4));
            *(float4*)&Ps[row * PB_STRIDE + c * 4] = v;
        }
        __syncthreads();

        // 64 FFMA per n; w-operands are warp-uniform scalar LDS (broadcast)
#pragma unroll
        for (int n = 0; n < B_NC; n++) {
            float4 b0 = *(const float4*)&Ps[n * PB_STRIDE + tx * 8];
            float4 b1 = *(const float4*)&Ps[n * PB_STRIDE + tx * 8 + 4];
            const float* erow = &Es[ty * 8 * ES_STRIDE + n];
#pragma unroll
            for (int i = 0; i < 8; i++) {
                float av = erow[i * ES_STRIDE];
                acc[i * 8 + 0] += av * b0.x;
                acc[i * 8 + 1] += av * b0.y;
                acc[i * 8 + 2] += av * b0.z;
                acc[i * 8 + 3] += av * b0.w;
                acc[i * 8 + 4] += av * b1.x;
                acc[i * 8 + 5] += av * b1.y;
                acc[i * 8 + 6] += av * b1.z;
                acc[i * 8 + 7] += av * b1.w;
            }
        }
    }

#pragma unroll
    for (int i = 0; i < 8; i++) {
        int r = ty * 8 + i;
        float* dst = emb + ((size_t)b * LL + l0 + r) * DD + tx * 8;
        *(float4*)dst = make_float4(acc[i * 8 + 0], acc[i * 8 + 1],
                                    acc[i * 8 + 2], acc[i * 8 + 3]);
        *(float4*)(dst + 4) = make_float4(acc[i * 8 + 4], acc[i * 8 + 5],
                                          acc[i * 8 + 6], acc[i * 8 + 7]);
    }
}

extern "C" void kernel_launch(void* const* d_in, const int* in_sizes, int n_in,
                              void* d_out, int out_size) {
    const float* x = (const float*)d_in[0];     // spk_decoder_out (B,L,D)
    const float* prof = (const float*)d_in[1];  // profile (B,N,D)
    const int* lens = (const int*)d_in[2];      // profile_lens (B,)

    float* emb = (float*)d_out;                          // (B,L,D)
    float* wout = (float*)d_out + (size_t)BB * LL * DD;  // (B,L,N)

    cudaFuncSetAttribute(cosattn_sim_kernel,
                         cudaFuncAttributeMaxDynamicSharedMemorySize, A_SMEM_BYTES);
    cudaFuncSetAttribute(cosattn_av_kernel,
                         cudaFuncAttributeMaxDynamicSharedMemorySize, B_SMEM_BYTES);

    pnorm_kernel<<<(BB * NN) / 8, 256>>>(prof);
    cosattn_sim_kernel<<<BB * (LL / A_TL), 256, A_SMEM_BYTES>>>(x, prof, lens, wout);
    cosattn_av_kernel<<<BB * (LL / B_TL), 256, B_SMEM_BYTES>>>(prof, wout, emb);
}

// round 8
// speedup vs baseline: 3.4685x; 1.9794x over previous
#include <cuda_runtime.h>
#include <math.h>
#include <float.h>
#include <stdint.h>

#define BB 16
#define LL 4096
#define NN 512
#define DD 256
#define EPSV 1e-8f

__device__ float g_pnorm[BB * NN];
__device__ float g_xnorm[BB * LL];
__device__ float g_rsum[BB * LL];

__device__ __forceinline__ uint32_t f2tf32(float f) {
    uint32_t u;
    asm("cvt.rna.tf32.f32 %0, %1;" : "=r"(u) : "f"(f));
    return u;
}

__device__ __forceinline__ void mma_tf32(float* d, const uint32_t* a, const uint32_t* bf) {
    asm volatile(
        "mma.sync.aligned.m16n8k8.row.col.f32.tf32.tf32.f32 "
        "{%0,%1,%2,%3}, {%4,%5,%6,%7}, {%8,%9}, {%0,%1,%2,%3};"
        : "+f"(d[0]), "+f"(d[1]), "+f"(d[2]), "+f"(d[3])
        : "r"(a[0]), "r"(a[1]), "r"(a[2]), "r"(a[3]), "r"(bf[0]), "r"(bf[1]));
}

// ---------------- norm kernels (fp32-exact) ----------------
__global__ void pnorm_kernel(const float* __restrict__ profile) {
    int w = (blockIdx.x * blockDim.x + threadIdx.x) >> 5;
    int lane = threadIdx.x & 31;
    if (w >= BB * NN) return;
    const float4* p = (const float4*)(profile + (size_t)w * DD);
    float4 v0 = p[lane], v1 = p[lane + 32];
    float s = v0.x * v0.x + v0.y * v0.y + v0.z * v0.z + v0.w * v0.w +
              v1.x * v1.x + v1.y * v1.y + v1.z * v1.z + v1.w * v1.w;
#pragma unroll
    for (int o = 16; o > 0; o >>= 1) s += __shfl_xor_sync(0xffffffffu, s, o);
    if (lane == 0) g_pnorm[w] = sqrtf(s);
}

__global__ void xnorm_kernel(const float* __restrict__ x) {
    int w = (blockIdx.x * blockDim.x + threadIdx.x) >> 5;
    int lane = threadIdx.x & 31;
    if (w >= BB * LL) return;
    const float4* p = (const float4*)(x + (size_t)w * DD);
    float4 v0 = p[lane], v1 = p[lane + 32];
    float s = v0.x * v0.x + v0.y * v0.y + v0.z * v0.z + v0.w * v0.w +
              v1.x * v1.x + v1.y * v1.y + v1.z * v1.z + v1.w * v1.w;
#pragma unroll
    for (int o = 16; o > 0; o >>= 1) s += __shfl_xor_sync(0xffffffffu, s, o);
    if (lane == 0) g_xnorm[w] = sqrtf(s);
}

// ---------------- Kernel S: sims via mma.sync tf32 ----------------
// smem floats:
#define S_XS 0                         // 64 x 260
#define S_PS (S_XS + 64 * 260)         // 32 x 264   = 16640
#define S_PN (S_PS + 32 * 264)         // 512        = 25088
#define S_XN (S_PN + NN)               // 64         = 25600
#define S_RSP (S_XN + 64)              // 4 x 64     = 25664
#define S_FLOATS (S_RSP + 256)         // 25920
#define S_BYTES (S_FLOATS * 4)         // 103680

__global__ __launch_bounds__(256, 2) void cosattn_sim_mma(
    const float* __restrict__ x, const float* __restrict__ prof,
    const int* __restrict__ lens, float* __restrict__ wout) {
    extern __shared__ float sm[];
    float* Xs = sm + S_XS;
    float* Ps = sm + S_PS;
    float* pns = sm + S_PN;
    float* xns = sm + S_XN;
    float* rsp = sm + S_RSP;

    int b = blockIdx.x >> 6;
    int l0 = (blockIdx.x & 63) * 64;
    int tid = threadIdx.x;
    int wid = tid >> 5, lane = tid & 31;
    int wm = wid & 1, wn = wid >> 1;          // 2 m-warps x 4 n-warps
    int qg = lane >> 2, qt = lane & 3;        // quad group / thread-in-quad

    // stage X tile (64 x 256), tf32-rounded, row-major stride 260
    const float* xg = x + ((size_t)b * LL + l0) * DD;
#pragma unroll
    for (int s = 0; s < 16; s++) {
        int idx = s * 256 + tid;
        int row = idx >> 6, c = idx & 63;
        float4 v = *(const float4*)(xg + (size_t)row * DD + c * 4);
        uint4 t = make_uint4(f2tf32(v.x), f2tf32(v.y), f2tf32(v.z), f2tf32(v.w));
        *(uint4*)&Xs[row * 260 + c * 4] = t;
    }
    for (int i = tid; i < NN; i += 256) pns[i] = g_pnorm[b * NN + i];
    if (tid < 64) xns[tid] = g_xnorm[(size_t)b * LL + l0 + tid];
    rsp[tid] = 0.f;
    int plen = __ldg(&lens[b]);
    __syncthreads();

    for (int nch = 0; nch < 2; nch++) {
        int n0 = nch * 256;
        float acc[64];
#pragma unroll
        for (int i = 0; i < 64; i++) acc[i] = 0.f;

        for (int kc = 0; kc < 8; kc++) {
            int k0 = kc * 32;
            __syncthreads();
            // transpose-stage P: rows n0..n0+255, cols k0..k0+31 -> Ps[k][n], stride 264
#pragma unroll
            for (int s = 0; s < 8; s++) {
                int idx = s * 256 + tid;
                int n = idx & 255, cq = idx >> 8;
                float4 v = __ldg((const float4*)(prof +
                    ((size_t)b * NN + n0 + n) * DD + k0 + cq * 4));
                Ps[(cq * 4 + 0) * 264 + n] = __uint_as_float(f2tf32(v.x));
                Ps[(cq * 4 + 1) * 264 + n] = __uint_as_float(f2tf32(v.y));
                Ps[(cq * 4 + 2) * 264 + n] = __uint_as_float(f2tf32(v.z));
                Ps[(cq * 4 + 3) * 264 + n] = __uint_as_float(f2tf32(v.w));
            }
            __syncthreads();

#pragma unroll
            for (int ks = 0; ks < 4; ks++) {
                int kk = k0 + ks * 8;
                uint32_t af[2][4];
#pragma unroll
                for (int mt = 0; mt < 2; mt++) {
                    int r = wm * 32 + mt * 16 + qg;
                    af[mt][0] = *(const uint32_t*)&Xs[r * 260 + kk + qt];
                    af[mt][1] = *(const uint32_t*)&Xs[(r + 8) * 260 + kk + qt];
                    af[mt][2] = *(const uint32_t*)&Xs[r * 260 + kk + qt + 4];
                    af[mt][3] = *(const uint32_t*)&Xs[(r + 8) * 260 + kk + qt + 4];
                }
#pragma unroll
                for (int nt = 0; nt < 8; nt++) {
                    int n = wn * 64 + nt * 8 + qg;
                    uint32_t bf[2];
                    bf[0] = *(const uint32_t*)&Ps[(ks * 8 + qt) * 264 + n];
                    bf[1] = *(const uint32_t*)&Ps[(ks * 8 + qt + 4) * 264 + n];
                    mma_tf32(&acc[(0 * 8 + nt) * 4], af[0], bf);
                    mma_tf32(&acc[(1 * 8 + nt) * 4], af[1], bf);
                }
            }
        }

        // epilogue: scale, mask, exp, write weights, deterministic rowsums
#pragma unroll
        for (int mt = 0; mt < 2; mt++) {
            int r0 = wm * 32 + mt * 16 + qg;
            float xr0 = xns[r0], xr1 = xns[r0 + 8];
            float sum0 = 0.f, sum1 = 0.f;
#pragma unroll
            for (int nt = 0; nt < 8; nt++) {
                int n = n0 + wn * 64 + nt * 8 + qt * 2;
                float pn0 = pns[n];
                float pn1 = pns[n + 1];
                const float* a = &acc[(mt * 8 + nt) * 4];
                float e0 = (n < plen) ? __expf(a[0] / fmaxf(xr0 * pn0, EPSV)) : 0.f;
                float e1 = (n + 1 < plen) ? __expf(a[1] / fmaxf(xr0 * pn1, EPSV)) : 0.f;
                float e2 = (n < plen) ? __expf(a[2] / fmaxf(xr1 * pn0, EPSV)) : 0.f;
                float e3 = (n + 1 < plen) ? __expf(a[3] / fmaxf(xr1 * pn1, EPSV)) : 0.f;
                sum0 += e0 + e1;
                sum1 += e2 + e3;
                float* w0 = wout + ((size_t)b * LL + l0 + r0) * NN + n;
                float* w1 = wout + ((size_t)b * LL + l0 + r0 + 8) * NN + n;
                *(float2*)w0 = make_float2(e0, e1);
                *(float2*)w1 = make_float2(e2, e3);
            }
            // quad reduction (lanes qt=0..3 share rows r0, r0+8)
#pragma unroll
            for (int o = 1; o < 4; o <<= 1) {
                sum0 += __shfl_xor_sync(0xffffffffu, sum0, o);
                sum1 += __shfl_xor_sync(0xffffffffu, sum1, o);
            }
            if (qt == 0) {
                rsp[wn * 64 + r0] += sum0;
                rsp[wn * 64 + r0 + 8] += sum1;
            }
        }
    }
    __syncthreads();
    if (tid < 64)
        g_rsum[(size_t)b * LL + l0 + tid] =
            rsp[tid] + rsp[64 + tid] + rsp[128 + tid] + rsp[192 + tid];
}

// ---------------- Kernel V: emb = (E/rsum) @ P via mma.sync tf32 ----------------
// smem floats:
#define V_ES 0                         // 64 x 36
#define V_PS (V_ES + 64 * 36)          // 32 x 264   = 2304
#define V_INV (V_PS + 32 * 264)        // 64         = 10752
#define V_FLOATS (V_INV + 64)          // 10816
#define V_BYTES (V_FLOATS * 4)         // 43264

__global__ __launch_bounds__(256, 2) void cosattn_av_mma(
    const float* __restrict__ prof, float* __restrict__ wout,
    float* __restrict__ emb) {
    extern __shared__ float sm[];
    float* Es = sm + V_ES;
    float* Ps = sm + V_PS;
    float* inv = sm + V_INV;

    int b = blockIdx.x >> 6;
    int l0 = (blockIdx.x & 63) * 64;
    int tid = threadIdx.x;
    int wid = tid >> 5, lane = tid & 31;
    int wm = wid & 1, wn = wid >> 1;
    int qg = lane >> 2, qt = lane & 3;

    if (tid < 64) inv[tid] = 1.0f / g_rsum[(size_t)b * LL + l0 + tid];

    float acc[64];
#pragma unroll
    for (int i = 0; i < 64; i++) acc[i] = 0.f;
    __syncthreads();

    for (int kc = 0; kc < 16; kc++) {
        int n0 = kc * 32;
        __syncthreads();
        // stage E chunk (64 x 32): normalize in place, round to tf32, stride 36
#pragma unroll
        for (int s = 0; s < 2; s++) {
            int idx = s * 256 + tid;
            int row = idx >> 3, c = idx & 7;
            float* gp = wout + ((size_t)b * LL + l0 + row) * NN + n0 + c * 4;
            float4 v = *(float4*)gp;
            float iv = inv[row];
            v.x *= iv; v.y *= iv; v.z *= iv; v.w *= iv;
            *(float4*)gp = v;
            uint4 t = make_uint4(f2tf32(v.x), f2tf32(v.y), f2tf32(v.z), f2tf32(v.w));
            *(uint4*)&Es[row * 36 + c * 4] = t;
        }
        // stage P chunk (32 n-rows x 256 d), n-major stride 264 (direct, no transpose)
#pragma unroll
        for (int s = 0; s < 8; s++) {
            int idx = s * 256 + tid;
            int n = idx >> 6, c = idx & 63;
            float4 v = __ldg((const float4*)(prof +
                ((size_t)b * NN + n0 + n) * DD + c * 4));
            uint4 t = make_uint4(f2tf32(v.x), f2tf32(v.y), f2tf32(v.z), f2tf32(v.w));
            *(uint4*)&Ps[n * 264 + c * 4] = t;
        }
        __syncthreads();

#pragma unroll
        for (int ks = 0; ks < 4; ks++) {
            int kk = ks * 8;
            uint32_t af[2][4];
#pragma unroll
            for (int mt = 0; mt < 2; mt++) {
                int r = wm * 32 + mt * 16 + qg;
                af[mt][0] = *(const uint32_t*)&Es[r * 36 + kk + qt];
                af[mt][1] = *(const uint32_t*)&Es[(r + 8) * 36 + kk + qt];
                af[mt][2] = *(const uint32_t*)&Es[r * 36 + kk + qt + 4];
                af[mt][3] = *(const uint32_t*)&Es[(r + 8) * 36 + kk + qt + 4];
            }
#pragma unroll
            for (int nt = 0; nt < 8; nt++) {
                int d = wn * 64 + nt * 8 + qg;
                uint32_t bf[2];
                bf[0] = *(const uint32_t*)&Ps[(kk + qt) * 264 + d];
                bf[1] = *(const uint32_t*)&Ps[(kk + qt + 4) * 264 + d];
                mma_tf32(&acc[(0 * 8 + nt) * 4], af[0], bf);
                mma_tf32(&acc[(1 * 8 + nt) * 4], af[1], bf);
            }
        }
    }

    // epilogue: write emb
#pragma unroll
    for (int mt = 0; mt < 2; mt++) {
        int r0 = wm * 32 + mt * 16 + qg;
#pragma unroll
        for (int nt = 0; nt < 8; nt++) {
            int d = wn * 64 + nt * 8 + qt * 2;
            const float* a = &acc[(mt * 8 + nt) * 4];
            float* e0 = emb + ((size_t)b * LL + l0 + r0) * DD + d;
            float* e1 = emb + ((size_t)b * LL + l0 + r0 + 8) * DD + d;
            *(float2*)e0 = make_float2(a[0], a[1]);
            *(float2*)e1 = make_float2(a[2], a[3]);
        }
    }
}

extern "C" void kernel_launch(void* const* d_in, const int* in_sizes, int n_in,
                              void* d_out, int out_size) {
    const float* x = (const float*)d_in[0];
    const float* prof = (const float*)d_in[1];
    const int* lens = (const int*)d_in[2];
    float* emb = (float*)d_out;
    float* wout = (float*)d_out + (size_t)BB * LL * DD;

    cudaFuncSetAttribute(cosattn_sim_mma, cudaFuncAttributeMaxDynamicSharedMemorySize, S_BYTES);
    cudaFuncSetAttribute(cosattn_av_mma, cudaFuncAttributeMaxDynamicSharedMemorySize, V_BYTES);

    pnorm_kernel<<<(BB * NN) / 8, 256>>>(prof);
    xnorm_kernel<<<(BB * LL) / 8, 256>>>(x);
    cosattn_sim_mma<<<BB * (LL / 64), 256, S_BYTES>>>(x, prof, lens, wout);
    cosattn_av_mma<<<BB * (LL / 64), 256, V_BYTES>>>(prof, wout, emb);
}

// round 10
// speedup vs baseline: 4.2607x; 1.2284x over previous
#include <cuda_runtime.h>
#include <math.h>
#include <float.h>
#include <stdint.h>

#define BB 16
#define LL 4096
#define NN 512
#define DD 256
#define EPSV 1e-8f

__device__ float g_pnorm[BB * NN];
__device__ float g_xnorm[BB * LL];
__device__ float g_ptf[BB * NN * DD];   // tf32-rounded profile (8MB)

__device__ __forceinline__ uint32_t smem_u32(const void* p) {
    uint32_t a;
    asm("{ .reg .u64 t; cvta.to.shared.u64 t, %1; cvt.u32.u64 %0, t; }" : "=r"(a) : "l"(p));
    return a;
}
__device__ __forceinline__ uint32_t f2tf32(float f) {
    uint32_t u;
    asm("cvt.rna.tf32.f32 %0, %1;" : "=r"(u) : "f"(f));
    return u;
}
__device__ __forceinline__ void cp16(uint32_t dst, const void* src) {
    asm volatile("cp.async.ca.shared.global [%0], [%1], 16;" :: "r"(dst), "l"(src));
}
#define CP_COMMIT() asm volatile("cp.async.commit_group;" ::: "memory")
#define CP_WAIT1()  asm volatile("cp.async.wait_group 1;" ::: "memory")
#define CP_WAIT0()  asm volatile("cp.async.wait_group 0;" ::: "memory")

__device__ __forceinline__ void mma_tf32(float* d, const uint32_t* a, const uint32_t* bf) {
    asm volatile(
        "mma.sync.aligned.m16n8k8.row.col.f32.tf32.tf32.f32 "
        "{%0,%1,%2,%3}, {%4,%5,%6,%7}, {%8,%9}, {%0,%1,%2,%3};"
        : "+f"(d[0]), "+f"(d[1]), "+f"(d[2]), "+f"(d[3])
        : "r"(a[0]), "r"(a[1]), "r"(a[2]), "r"(a[3]), "r"(bf[0]), "r"(bf[1]));
}

// ---------------- prepasses ----------------
__global__ void pnorm_kernel(const float* __restrict__ profile) {
    int w = (blockIdx.x * blockDim.x + threadIdx.x) >> 5;
    int lane = threadIdx.x & 31;
    if (w >= BB * NN) return;
    const float4* p = (const float4*)(profile + (size_t)w * DD);
    float4 v0 = p[lane], v1 = p[lane + 32];
    float s = v0.x * v0.x + v0.y * v0.y + v0.z * v0.z + v0.w * v0.w +
              v1.x * v1.x + v1.y * v1.y + v1.z * v1.z + v1.w * v1.w;
#pragma unroll
    for (int o = 16; o > 0; o >>= 1) s += __shfl_xor_sync(0xffffffffu, s, o);
    if (lane == 0) g_pnorm[w] = sqrtf(s);
}

__global__ void xnorm_kernel(const float* __restrict__ x) {
    int w = (blockIdx.x * blockDim.x + threadIdx.x) >> 5;
    int lane = threadIdx.x & 31;
    if (w >= BB * LL) return;
    const float4* p = (const float4*)(x + (size_t)w * DD);
    float4 v0 = p[lane], v1 = p[lane + 32];
    float s = v0.x * v0.x + v0.y * v0.y + v0.z * v0.z + v0.w * v0.w +
              v1.x * v1.x + v1.y * v1.y + v1.z * v1.z + v1.w * v1.w;
#pragma unroll
    for (int o = 16; o > 0; o >>= 1) s += __shfl_xor_sync(0xffffffffu, s, o);
    if (lane == 0) g_xnorm[w] = sqrtf(s);
}

__global__ void ptf_kernel(const float* __restrict__ prof) {
    int idx = blockIdx.x * 256 + threadIdx.x;      // BB*NN*DD/4 = 524288 float4
    float4 v = ((const float4*)prof)[idx];
    uint4 t = make_uint4(f2tf32(v.x), f2tf32(v.y), f2tf32(v.z), f2tf32(v.w));
    ((uint4*)g_ptf)[idx] = t;
}

// ---------------- fused kernel ----------------
// smem layout (bytes):
#define ES_B 0                          // 64 x 516 f32 = 132096
#define XB_B 132096                     // 2 x (64 x 36) f32 = 2 x 9216
#define PB_B 150528                     // 2 x (256 x 36) f32 = 2 x 36864
#define PB2_B 132096                    // phase 2: 2 x (32 x 264) f32 = 2 x 33792 (alias)
#define PNS_B 224256                    // 512 f32
#define XNS_B 226304                    // 64 f32
#define INV_B 226560                    // 64 f32
#define RSP_B 226816                    // 256 f32
#define F_SMEM 227840

__global__ __launch_bounds__(256, 1) void cosattn_fused(
    const float* __restrict__ x, const int* __restrict__ lens,
    float* __restrict__ wout, float* __restrict__ emb) {
    extern __shared__ char smc[];
    const uint32_t smb = smem_u32(smc);
    float* Es = (float*)(smc + ES_B);
    float* pns = (float*)(smc + PNS_B);
    float* xns = (float*)(smc + XNS_B);
    float* inv = (float*)(smc + INV_B);
    float* rsp = (float*)(smc + RSP_B);

    int b = blockIdx.x >> 6;
    int l0 = (blockIdx.x & 63) * 64;
    int tid = threadIdx.x;
    int wid = tid >> 5, lane = tid & 31;
    int wm = wid & 1, wn = wid >> 1;          // 2 m-warps x 4 n-warps
    int qg = lane >> 2, qt = lane & 3;

    for (int i = tid; i < NN; i += 256) pns[i] = g_pnorm[b * NN + i];
    if (tid < 64) xns[tid] = g_xnorm[(size_t)b * LL + l0 + tid];
    rsp[tid] = 0.f;
    int plen = __ldg(&lens[b]);

    const float* xg = x + ((size_t)b * LL + l0) * DD;
    const float* pg = g_ptf + (size_t)b * NN * DD;

    // ---- phase 1: sims, 16 chunks (nch 0..1 of 256n) x (kc 0..7 of 32k) ----
#define ISSUE1(it) do {                                                          \
    int _nch = (it) >> 3, _kc = (it) & 7, _bi = (it) & 1;                        \
    int _k0 = _kc * 32;                                                          \
    _Pragma("unroll")                                                            \
    for (int s = 0; s < 2; s++) {                                                \
        int idx = s * 256 + tid;                                                 \
        int row = idx >> 3, c = idx & 7;                                         \
        cp16(smb + XB_B + _bi * 9216 + (row * 36 + c * 4) * 4,                   \
             xg + (size_t)row * DD + _k0 + c * 4);                               \
    }                                                                            \
    _Pragma("unroll")                                                            \
    for (int s = 0; s < 8; s++) {                                                \
        int idx = s * 256 + tid;                                                 \
        int row = idx >> 3, c = idx & 7;                                         \
        cp16(smb + PB_B + _bi * 36864 + (row * 36 + c * 4) * 4,                  \
             pg + ((size_t)(_nch * 256 + row)) * DD + _k0 + c * 4);              \
    }                                                                            \
    CP_COMMIT();                                                                 \
} while (0)

    float acc[64];
#pragma unroll
    for (int i = 0; i < 64; i++) acc[i] = 0.f;

    ISSUE1(0);
    for (int it = 0; it < 16; ++it) {
        if (it < 15) { ISSUE1(it + 1); CP_WAIT1(); } else { CP_WAIT0(); }
        __syncthreads();
        int bi = it & 1;
        const float* Xb = (const float*)(smc + XB_B + bi * 9216);
        const float* Pb = (const float*)(smc + PB_B + bi * 36864);
#pragma unroll
        for (int ks = 0; ks < 4; ks++) {
            int kk = ks * 8;
            uint32_t af[2][4];
#pragma unroll
            for (int mt = 0; mt < 2; mt++) {
                int r = wm * 32 + mt * 16 + qg;
                af[mt][0] = f2tf32(Xb[r * 36 + kk + qt]);
                af[mt][1] = f2tf32(Xb[(r + 8) * 36 + kk + qt]);
                af[mt][2] = f2tf32(Xb[r * 36 + kk + qt + 4]);
                af[mt][3] = f2tf32(Xb[(r + 8) * 36 + kk + qt + 4]);
            }
#pragma unroll
            for (int nt = 0; nt < 8; nt++) {
                int n = wn * 64 + nt * 8 + qg;
                uint32_t bf[2];
                bf[0] = __float_as_uint(Pb[n * 36 + kk + qt]);
                bf[1] = __float_as_uint(Pb[n * 36 + kk + qt + 4]);
                mma_tf32(&acc[(0 * 8 + nt) * 4], af[0], bf);
                mma_tf32(&acc[(1 * 8 + nt) * 4], af[1], bf);
            }
        }
        if ((it & 7) == 7) {
            // epilogue for n-chunk nch = it>>3: exp into Es + rowsums
            int nch = it >> 3;
#pragma unroll
            for (int mt = 0; mt < 2; mt++) {
                int r0 = wm * 32 + mt * 16 + qg;
                float xr0 = xns[r0], xr1 = xns[r0 + 8];
                float sum0 = 0.f, sum1 = 0.f;
#pragma unroll
                for (int nt = 0; nt < 8; nt++) {
                    int n = nch * 256 + wn * 64 + nt * 8 + qt * 2;
                    float pn0 = pns[n], pn1 = pns[n + 1];
                    float* a = &acc[(mt * 8 + nt) * 4];
                    float e0 = (n < plen) ? __expf(a[0] / fmaxf(xr0 * pn0, EPSV)) : 0.f;
                    float e1 = (n + 1 < plen) ? __expf(a[1] / fmaxf(xr0 * pn1, EPSV)) : 0.f;
                    float e2 = (n < plen) ? __expf(a[2] / fmaxf(xr1 * pn0, EPSV)) : 0.f;
                    float e3 = (n + 1 < plen) ? __expf(a[3] / fmaxf(xr1 * pn1, EPSV)) : 0.f;
                    sum0 += e0 + e1;
                    sum1 += e2 + e3;
                    *(float2*)&Es[r0 * 516 + n] = make_float2(e0, e1);
                    *(float2*)&Es[(r0 + 8) * 516 + n] = make_float2(e2, e3);
                    a[0] = a[1] = a[2] = a[3] = 0.f;   // reset for next nch / phase 2
                }
#pragma unroll
                for (int o = 1; o < 4; o <<= 1) {
                    sum0 += __shfl_xor_sync(0xffffffffu, sum0, o);
                    sum1 += __shfl_xor_sync(0xffffffffu, sum1, o);
                }
                if (qt == 0) {
                    rsp[wn * 64 + r0] += sum0;
                    rsp[wn * 64 + r0 + 8] += sum1;
                }
            }
        }
        __syncthreads();
    }

    // ---- transition: inv, first phase-2 issue, normalized wout write ----
#define ISSUE2(it) do {                                                          \
    int _bi = (it) & 1;                                                          \
    _Pragma("unroll")                                                            \
    for (int s = 0; s < 8; s++) {                                                \
        int idx = s * 256 + tid;                                                 \
        int row = idx >> 6, c = idx & 63;                                        \
        cp16(smb + PB2_B + _bi * 33792 + (row * 264 + c * 4) * 4,                \
             pg + ((size_t)((it) * 32 + row)) * DD + c * 4);                     \
    }                                                                            \
    CP_COMMIT();                                                                 \
} while (0)

    if (tid < 64)
        inv[tid] = 1.0f / (rsp[tid] + rsp[64 + tid] + rsp[128 + tid] + rsp[192 + tid]);
    ISSUE2(0);
    __syncthreads();

    // write normalized weights (full precision), coalesced; overlaps cp.async
    {
        float* wbase = wout + ((size_t)b * LL + l0) * NN;
#pragma unroll
        for (int s = 0; s < 32; s++) {
            int idx = s * 256 + tid;
            int row = idx >> 7, c4 = idx & 127;
            float4 v = *(const float4*)&Es[row * 516 + c4 * 4];
            float iv = inv[row];
            *(float4*)(wbase + (size_t)row * NN + c4 * 4) =
                make_float4(v.x * iv, v.y * iv, v.z * iv, v.w * iv);
        }
    }

    // ---- phase 2: emb = (E @ P) * inv, K = 512 over 16 chunks of 32 ----
    for (int it = 0; it < 16; ++it) {
        if (it < 15) { ISSUE2(it + 1); CP_WAIT1(); } else { CP_WAIT0(); }
        __syncthreads();
        int n0 = it * 32;
        const float* Pb = (const float*)(smc + PB2_B + (it & 1) * 33792);
#pragma unroll
        for (int ks = 0; ks < 4; ks++) {
            int kk = ks * 8;
            uint32_t af[2][4];
#pragma unroll
            for (int mt = 0; mt < 2; mt++) {
                int r = wm * 32 + mt * 16 + qg;
                af[mt][0] = f2tf32(Es[r * 516 + n0 + kk + qt]);
                af[mt][1] = f2tf32(Es[(r + 8) * 516 + n0 + kk + qt]);
                af[mt][2] = f2tf32(Es[r * 516 + n0 + kk + qt + 4]);
                af[mt][3] = f2tf32(Es[(r + 8) * 516 + n0 + kk + qt + 4]);
            }
#pragma unroll
            for (int nt = 0; nt < 8; nt++) {
                int d = wn * 64 + nt * 8 + qg;
                uint32_t bf[2];
                bf[0] = __float_as_uint(Pb[(kk + qt) * 264 + d]);
                bf[1] = __float_as_uint(Pb[(kk + qt + 4) * 264 + d]);
                mma_tf32(&acc[(0 * 8 + nt) * 4], af[0], bf);
                mma_tf32(&acc[(1 * 8 + nt) * 4], af[1], bf);
            }
        }
        __syncthreads();
    }

    // epilogue: emb writes scaled by inv
#pragma unroll
    for (int mt = 0; mt < 2; mt++) {
        int r0 = wm * 32 + mt * 16 + qg;
        float iv0 = inv[r0], iv1 = inv[r0 + 8];
#pragma unroll
        for (int nt = 0; nt < 8; nt++) {
            int d = wn * 64 + nt * 8 + qt * 2;
            const float* a = &acc[(mt * 8 + nt) * 4];
            float* e0 = emb + ((size_t)b * LL + l0 + r0) * DD + d;
            float* e1 = emb + ((size_t)b * LL + l0 + r0 + 8) * DD + d;
            *(float2*)e0 = make_float2(a[0] * iv0, a[1] * iv0);
            *(float2*)e1 = make_float2(a[2] * iv1, a[3] * iv1);
        }
    }
}

extern "C" void kernel_launch(void* const* d_in, const int* in_sizes, int n_in,
                              void* d_out, int out_size) {
    const float* x = (const float*)d_in[0];
    const float* prof = (const float*)d_in[1];
    const int* lens = (const int*)d_in[2];
    float* emb = (float*)d_out;
    float* wout = (float*)d_out + (size_t)BB * LL * DD;

    cudaFuncSetAttribute(cosattn_fused, cudaFuncAttributeMaxDynamicSharedMemorySize, F_SMEM);

    pnorm_kernel<<<(BB * NN) / 8, 256>>>(prof);
    xnorm_kernel<<<(BB * LL) / 8, 256>>>(x);
    ptf_kernel<<<(BB * NN * DD) / 1024, 256>>>(prof);
    cosattn_fused<<<BB * (LL / 64), 256, F_SMEM>>>(x, lens, wout, emb);
}

// round 11
// speedup vs baseline: 7.2852x; 1.7099x over previous
#include <cuda_runtime.h>
#include <cuda_fp16.h>
#include <math.h>
#include <float.h>
#include <stdint.h>

#define BB 16
#define LL 4096
#define NN 512
#define DD 256
#define EPSV 1e-8f

__device__ float g_pnorm[BB * NN];
__device__ float g_xnorm[BB * LL];
__device__ __half g_xh[BB * LL * DD];    // 32MB fp16 X
__device__ __half g_ph[BB * NN * DD];    // 4MB fp16 P [b][n][d]
__device__ __half g_pth[BB * DD * NN];   // 4MB fp16 P^T [b][d][n]

__device__ __forceinline__ uint32_t smem_u32(const void* p) {
    uint32_t a;
    asm("{ .reg .u64 t; cvta.to.shared.u64 t, %1; cvt.u32.u64 %0, t; }" : "=r"(a) : "l"(p));
    return a;
}
__device__ __forceinline__ void cp16(uint32_t dst, const void* src) {
    asm volatile("cp.async.ca.shared.global [%0], [%1], 16;" :: "r"(dst), "l"(src));
}
#define CP_COMMIT() asm volatile("cp.async.commit_group;" ::: "memory")
#define CP_WAIT1()  asm volatile("cp.async.wait_group 1;" ::: "memory")
#define CP_WAIT0()  asm volatile("cp.async.wait_group 0;" ::: "memory")

__device__ __forceinline__ void mma_f16(float* d, const uint32_t* a, const uint32_t* b) {
    asm volatile(
        "mma.sync.aligned.m16n8k16.row.col.f32.f16.f16.f32 "
        "{%0,%1,%2,%3}, {%4,%5,%6,%7}, {%8,%9}, {%0,%1,%2,%3};"
        : "+f"(d[0]), "+f"(d[1]), "+f"(d[2]), "+f"(d[3])
        : "r"(a[0]), "r"(a[1]), "r"(a[2]), "r"(a[3]), "r"(b[0]), "r"(b[1]));
}

// ---------------- prepasses ----------------
// X: norms + fp16 convert (one read of X)
__global__ void cvtx_kernel(const float* __restrict__ x) {
    int w = (blockIdx.x * blockDim.x + threadIdx.x) >> 5;
    int lane = threadIdx.x & 31;
    if (w >= BB * LL) return;
    const float4* src = (const float4*)(x + (size_t)w * DD);
    float4 v0 = src[lane], v1 = src[lane + 32];
    float s = v0.x * v0.x + v0.y * v0.y + v0.z * v0.z + v0.w * v0.w +
              v1.x * v1.x + v1.y * v1.y + v1.z * v1.z + v1.w * v1.w;
#pragma unroll
    for (int o = 16; o > 0; o >>= 1) s += __shfl_xor_sync(0xffffffffu, s, o);
    if (lane == 0) g_xnorm[w] = sqrtf(s);
    __half2* dst = (__half2*)(g_xh + (size_t)w * DD);
    dst[2 * lane] = __floats2half2_rn(v0.x, v0.y);
    dst[2 * lane + 1] = __floats2half2_rn(v0.z, v0.w);
    dst[64 + 2 * lane] = __floats2half2_rn(v1.x, v1.y);
    dst[64 + 2 * lane + 1] = __floats2half2_rn(v1.z, v1.w);
}

// P: norms + fp16 convert
__global__ void cvtp_kernel(const float* __restrict__ prof) {
    int w = (blockIdx.x * blockDim.x + threadIdx.x) >> 5;
    int lane = threadIdx.x & 31;
    if (w >= BB * NN) return;
    const float4* src = (const float4*)(prof + (size_t)w * DD);
    float4 v0 = src[lane], v1 = src[lane + 32];
    float s = v0.x * v0.x + v0.y * v0.y + v0.z * v0.z + v0.w * v0.w +
              v1.x * v1.x + v1.y * v1.y + v1.z * v1.z + v1.w * v1.w;
#pragma unroll
    for (int o = 16; o > 0; o >>= 1) s += __shfl_xor_sync(0xffffffffu, s, o);
    if (lane == 0) g_pnorm[w] = sqrtf(s);
    __half2* dst = (__half2*)(g_ph + (size_t)w * DD);
    dst[2 * lane] = __floats2half2_rn(v0.x, v0.y);
    dst[2 * lane + 1] = __floats2half2_rn(v0.z, v0.w);
    dst[64 + 2 * lane] = __floats2half2_rn(v1.x, v1.y);
    dst[64 + 2 * lane + 1] = __floats2half2_rn(v1.z, v1.w);
}

// P^T: [b][n][d] -> [b][d][n], 32-n tiles via smem
__global__ void ptr_kernel() {
    __shared__ __half tile[32][264];
    int b = blockIdx.x >> 4, n0 = (blockIdx.x & 15) * 32;
    int tid = threadIdx.x, wid = tid >> 5, lane = tid & 31;
#pragma unroll
    for (int s = 0; s < 4; s++) {
        int idx = s * 256 + tid;
        int row = idx >> 5, c = idx & 31;
        *(uint4*)&tile[row][c * 8] =
            *(const uint4*)(g_ph + ((size_t)(b * NN + n0 + row)) * DD + c * 8);
    }
    __syncthreads();
#pragma unroll
    for (int i = 0; i < 32; i++) {
        int d = wid * 32 + i;
        if (lane < 16) {
            __half2 v = __halves2half2(tile[2 * lane][d], tile[2 * lane + 1][d]);
            ((__half2*)(g_pth + ((size_t)(b * DD + d)) * NN + n0))[lane] = v;
        }
    }
}

// ---------------- fused kernel ----------------
// smem layout (bytes):
#define ESH_B 0                      // 64 x 520 fp16 = 66560
#define XB_B 66560                   // 2 x (64 x 72 fp16) = 2 x 9216
#define PB_B 84992                   // 2 x (256 x 72 fp16) = 2 x 36864
#define PT_B 66560                   // phase 2 alias: 2 x 36864
#define PNS_B 158720                 // 512 f32
#define XNS_B 160768                 // 64 f32
#define INV_B 161024                 // 64 f32
#define RSP_B 161280                 // 256 f32
#define F_SMEM 162304

__global__ __launch_bounds__(256, 1) void cosattn_fused(
    const int* __restrict__ lens, float* __restrict__ wout, float* __restrict__ emb) {
    extern __shared__ char smc[];
    const uint32_t smb = smem_u32(smc);
    __half* Esh = (__half*)(smc + ESH_B);
    float* pns = (float*)(smc + PNS_B);
    float* xns = (float*)(smc + XNS_B);
    float* inv = (float*)(smc + INV_B);
    float* rsp = (float*)(smc + RSP_B);

    int b = blockIdx.x >> 6;
    int l0 = (blockIdx.x & 63) * 64;
    int tid = threadIdx.x;
    int wid = tid >> 5, lane = tid & 31;
    int wm = wid & 1, wn = wid >> 1;          // 2 m-warps x 4 n-warps
    int qg = lane >> 2, qt = lane & 3;

    for (int i = tid; i < NN; i += 256) pns[i] = g_pnorm[b * NN + i];
    if (tid < 64) xns[tid] = g_xnorm[(size_t)b * LL + l0 + tid];
    rsp[tid] = 0.f;
    int plen = __ldg(&lens[b]);

    // ---- phase 1: sims, 8 chunks (nch 0..1 x kc 0..3 of 64k) ----
#define ISSUE1(it) do {                                                          \
    int _nch = (it) >> 2, _kc = (it) & 3, _bi = (it) & 1;                        \
    int _k0 = _kc * 64;                                                          \
    const __half* _xs = g_xh + ((size_t)(b * LL + l0)) * DD + _k0;               \
    _Pragma("unroll")                                                            \
    for (int s = 0; s < 2; s++) {                                                \
        int idx = s * 256 + tid;                                                 \
        int row = idx >> 3, c = idx & 7;                                         \
        cp16(smb + XB_B + _bi * 9216 + (row * 72 + c * 8) * 2,                   \
             _xs + (size_t)row * DD + c * 8);                                    \
    }                                                                            \
    const __half* _ps = g_ph + ((size_t)(b * NN + _nch * 256)) * DD + _k0;       \
    _Pragma("unroll")                                                            \
    for (int s = 0; s < 8; s++) {                                                \
        int idx = s * 256 + tid;                                                 \
        int row = idx >> 3, c = idx & 7;                                         \
        cp16(smb + PB_B + _bi * 36864 + (row * 72 + c * 8) * 2,                  \
             _ps + (size_t)row * DD + c * 8);                                    \
    }                                                                            \
    CP_COMMIT();                                                                 \
} while (0)

    float acc[64];
#pragma unroll
    for (int i = 0; i < 64; i++) acc[i] = 0.f;

    ISSUE1(0);
    for (int it = 0; it < 8; ++it) {
        if (it < 7) { ISSUE1(it + 1); CP_WAIT1(); } else { CP_WAIT0(); }
        __syncthreads();
        int bi = it & 1;
        const __half* Xb = (const __half*)(smc + XB_B + bi * 9216);
        const __half* Pb = (const __half*)(smc + PB_B + bi * 36864);
#pragma unroll
        for (int ks = 0; ks < 4; ks++) {
            int kk = ks * 16;
            uint32_t af[2][4];
#pragma unroll
            for (int mt = 0; mt < 2; mt++) {
                int r = wm * 32 + mt * 16 + qg;
                af[mt][0] = *(const uint32_t*)&Xb[r * 72 + kk + 2 * qt];
                af[mt][1] = *(const uint32_t*)&Xb[(r + 8) * 72 + kk + 2 * qt];
                af[mt][2] = *(const uint32_t*)&Xb[r * 72 + kk + 2 * qt + 8];
                af[mt][3] = *(const uint32_t*)&Xb[(r + 8) * 72 + kk + 2 * qt + 8];
            }
#pragma unroll
            for (int nt = 0; nt < 8; nt++) {
                int n = wn * 64 + nt * 8 + qg;
                uint32_t bf[2];
                bf[0] = *(const uint32_t*)&Pb[n * 72 + kk + 2 * qt];
                bf[1] = *(const uint32_t*)&Pb[n * 72 + kk + 2 * qt + 8];
                mma_f16(&acc[(0 * 8 + nt) * 4], af[0], bf);
                mma_f16(&acc[(1 * 8 + nt) * 4], af[1], bf);
            }
        }
        if ((it & 3) == 3) {
            int nch = it >> 2;
#pragma unroll
            for (int mt = 0; mt < 2; mt++) {
                int r0 = wm * 32 + mt * 16 + qg;
                float xr0 = xns[r0], xr1 = xns[r0 + 8];
                float sum0 = 0.f, sum1 = 0.f;
#pragma unroll
                for (int nt = 0; nt < 8; nt++) {
                    int n = nch * 256 + wn * 64 + nt * 8 + qt * 2;
                    float pn0 = pns[n], pn1 = pns[n + 1];
                    float* a = &acc[(mt * 8 + nt) * 4];
                    float e0 = (n < plen) ? __expf(a[0] / fmaxf(xr0 * pn0, EPSV)) : 0.f;
                    float e1 = (n + 1 < plen) ? __expf(a[1] / fmaxf(xr0 * pn1, EPSV)) : 0.f;
                    float e2 = (n < plen) ? __expf(a[2] / fmaxf(xr1 * pn0, EPSV)) : 0.f;
                    float e3 = (n + 1 < plen) ? __expf(a[3] / fmaxf(xr1 * pn1, EPSV)) : 0.f;
                    sum0 += e0 + e1;
                    sum1 += e2 + e3;
                    *(__half2*)&Esh[r0 * 520 + n] = __floats2half2_rn(e0, e1);
                    *(__half2*)&Esh[(r0 + 8) * 520 + n] = __floats2half2_rn(e2, e3);
                    a[0] = a[1] = a[2] = a[3] = 0.f;
                }
#pragma unroll
                for (int o = 1; o < 4; o <<= 1) {
                    sum0 += __shfl_xor_sync(0xffffffffu, sum0, o);
                    sum1 += __shfl_xor_sync(0xffffffffu, sum1, o);
                }
                if (qt == 0) {
                    rsp[wn * 64 + r0] += sum0;
                    rsp[wn * 64 + r0 + 8] += sum1;
                }
            }
        }
        __syncthreads();
    }

    // ---- transition ----
#define ISSUE2(it) do {                                                          \
    int _bi = (it) & 1;                                                          \
    const __half* _ts = g_pth + (size_t)b * DD * NN + (it) * 64;                 \
    _Pragma("unroll")                                                            \
    for (int s = 0; s < 8; s++) {                                                \
        int idx = s * 256 + tid;                                                 \
        int row = idx >> 3, c = idx & 7;                                         \
        cp16(smb + PT_B + _bi * 36864 + (row * 72 + c * 8) * 2,                  \
             _ts + (size_t)row * NN + c * 8);                                    \
    }                                                                            \
    CP_COMMIT();                                                                 \
} while (0)

    if (tid < 64)
        inv[tid] = 1.0f / (rsp[tid] + rsp[64 + tid] + rsp[128 + tid] + rsp[192 + tid]);
    ISSUE2(0);
    __syncthreads();

    // normalized weights out (overlaps cp.async flight)
    {
        const __half2* Eh2 = (const __half2*)Esh;   // row stride 260 half2
        float* wbase = wout + ((size_t)b * LL + l0) * NN;
#pragma unroll
        for (int s = 0; s < 64; s++) {
            int idx = s * 256 + tid;
            int row = idx >> 8, c2 = idx & 255;
            float2 v = __half22float2(Eh2[row * 260 + c2]);
            float iv = inv[row];
            *(float2*)(wbase + (size_t)row * NN + c2 * 2) = make_float2(v.x * iv, v.y * iv);
        }
    }

    // ---- phase 2: emb = (E @ P) * inv, K=512 over 8 chunks of 64 ----
    for (int it = 0; it < 8; ++it) {
        if (it < 7) { ISSUE2(it + 1); CP_WAIT1(); } else { CP_WAIT0(); }
        __syncthreads();
        int bi = it & 1;
        const __half* Ptb = (const __half*)(smc + PT_B + bi * 36864);
        int nb = it * 64;
#pragma unroll
        for (int ks = 0; ks < 4; ks++) {
            int kk = ks * 16;
            uint32_t af[2][4];
#pragma unroll
            for (int mt = 0; mt < 2; mt++) {
                int r = wm * 32 + mt * 16 + qg;
                af[mt][0] = *(const uint32_t*)&Esh[r * 520 + nb + kk + 2 * qt];
                af[mt][1] = *(const uint32_t*)&Esh[(r + 8) * 520 + nb + kk + 2 * qt];
                af[mt][2] = *(const uint32_t*)&Esh[r * 520 + nb + kk + 2 * qt + 8];
                af[mt][3] = *(const uint32_t*)&Esh[(r + 8) * 520 + nb + kk + 2 * qt + 8];
            }
#pragma unroll
            for (int nt = 0; nt < 8; nt++) {
                int d = wn * 64 + nt * 8 + qg;
                uint32_t bf[2];
                bf[0] = *(const uint32_t*)&Ptb[d * 72 + kk + 2 * qt];
                bf[1] = *(const uint32_t*)&Ptb[d * 72 + kk + 2 * qt + 8];
                mma_f16(&acc[(0 * 8 + nt) * 4], af[0], bf);
                mma_f16(&acc[(1 * 8 + nt) * 4], af[1], bf);
            }
        }
        __syncthreads();
    }

    // epilogue: emb scaled by inv
#pragma unroll
    for (int mt = 0; mt < 2; mt++) {
        int r0 = wm * 32 + mt * 16 + qg;
        float iv0 = inv[r0], iv1 = inv[r0 + 8];
#pragma unroll
        for (int nt = 0; nt < 8; nt++) {
            int d = wn * 64 + nt * 8 + qt * 2;
            const float* a = &acc[(mt * 8 + nt) * 4];
            float* e0 = emb + ((size_t)b * LL + l0 + r0) * DD + d;
            float* e1 = emb + ((size_t)b * LL + l0 + r0 + 8) * DD + d;
            *(float2*)e0 = make_float2(a[0] * iv0, a[1] * iv0);
            *(float2*)e1 = make_float2(a[2] * iv1, a[3] * iv1);
        }
    }
}

extern "C" void kernel_launch(void* const* d_in, const int* in_sizes, int n_in,
                              void* d_out, int out_size) {
    const float* x = (const float*)d_in[0];
    const float* prof = (const float*)d_in[1];
    const int* lens = (const int*)d_in[2];
    float* emb = (float*)d_out;
    float* wout = (float*)d_out + (size_t)BB * LL * DD;

    cudaFuncSetAttribute(cosattn_fused, cudaFuncAttributeMaxDynamicSharedMemorySize, F_SMEM);

    cvtx_kernel<<<(BB * LL) / 8, 256>>>(x);
    cvtp_kernel<<<(BB * NN) / 8, 256>>>(prof);
    ptr_kernel<<<BB * (NN / 32), 256>>>();
    cosattn_fused<<<BB * (LL / 64), 256, F_SMEM>>>(lens, wout, emb);
}

// round 12
// speedup vs baseline: 7.4215x; 1.0187x over previous
#include <cuda_runtime.h>
#include <cuda_fp16.h>
#include <math.h>
#include <float.h>
#include <stdint.h>

#define BB 16
#define LL 4096
#define NN 512
#define DD 256
#define EPSV 1e-8f

__device__ float g_pnorm[BB * NN];
__device__ float g_xnorm[BB * LL];
__device__ __half g_xh[BB * LL * DD];    // 32MB fp16 X
__device__ __half g_ph[BB * NN * DD];    // 4MB fp16 P [b][n][d]
__device__ __half g_pth[BB * DD * NN];   // 4MB fp16 P^T [b][d][n]

__device__ __forceinline__ uint32_t smem_u32(const void* p) {
    uint32_t a;
    asm("{ .reg .u64 t; cvta.to.shared.u64 t, %1; cvt.u32.u64 %0, t; }" : "=r"(a) : "l"(p));
    return a;
}
__device__ __forceinline__ void cp16(uint32_t dst, const void* src) {
    asm volatile("cp.async.ca.shared.global [%0], [%1], 16;" :: "r"(dst), "l"(src));
}
#define CP_COMMIT() asm volatile("cp.async.commit_group;" ::: "memory")
#define CP_WAIT1()  asm volatile("cp.async.wait_group 1;" ::: "memory")
#define CP_WAIT0()  asm volatile("cp.async.wait_group 0;" ::: "memory")

__device__ __forceinline__ void mma_f16(float* d, const uint32_t* a, const uint32_t* b) {
    asm volatile(
        "mma.sync.aligned.m16n8k16.row.col.f32.f16.f16.f32 "
        "{%0,%1,%2,%3}, {%4,%5,%6,%7}, {%8,%9}, {%0,%1,%2,%3};"
        : "+f"(d[0]), "+f"(d[1]), "+f"(d[2]), "+f"(d[3])
        : "r"(a[0]), "r"(a[1]), "r"(a[2]), "r"(a[3]), "r"(b[0]), "r"(b[1]));
}

// ---------------- prepasses ----------------
__global__ void cvtx_kernel(const float* __restrict__ x) {
    int w = (blockIdx.x * blockDim.x + threadIdx.x) >> 5;
    int lane = threadIdx.x & 31;
    if (w >= BB * LL) return;
    const float4* src = (const float4*)(x + (size_t)w * DD);
    float4 v0 = src[lane], v1 = src[lane + 32];
    float s = v0.x * v0.x + v0.y * v0.y + v0.z * v0.z + v0.w * v0.w +
              v1.x * v1.x + v1.y * v1.y + v1.z * v1.z + v1.w * v1.w;
#pragma unroll
    for (int o = 16; o > 0; o >>= 1) s += __shfl_xor_sync(0xffffffffu, s, o);
    if (lane == 0) g_xnorm[w] = sqrtf(s);
    __half2* dst = (__half2*)(g_xh + (size_t)w * DD);
    dst[2 * lane] = __floats2half2_rn(v0.x, v0.y);
    dst[2 * lane + 1] = __floats2half2_rn(v0.z, v0.w);
    dst[64 + 2 * lane] = __floats2half2_rn(v1.x, v1.y);
    dst[64 + 2 * lane + 1] = __floats2half2_rn(v1.z, v1.w);
}

__global__ void cvtp_kernel(const float* __restrict__ prof) {
    int w = (blockIdx.x * blockDim.x + threadIdx.x) >> 5;
    int lane = threadIdx.x & 31;
    if (w >= BB * NN) return;
    const float4* src = (const float4*)(prof + (size_t)w * DD);
    float4 v0 = src[lane], v1 = src[lane + 32];
    float s = v0.x * v0.x + v0.y * v0.y + v0.z * v0.z + v0.w * v0.w +
              v1.x * v1.x + v1.y * v1.y + v1.z * v1.z + v1.w * v1.w;
#pragma unroll
    for (int o = 16; o > 0; o >>= 1) s += __shfl_xor_sync(0xffffffffu, s, o);
    if (lane == 0) g_pnorm[w] = sqrtf(s);
    __half2* dst = (__half2*)(g_ph + (size_t)w * DD);
    dst[2 * lane] = __floats2half2_rn(v0.x, v0.y);
    dst[2 * lane + 1] = __floats2half2_rn(v0.z, v0.w);
    dst[64 + 2 * lane] = __floats2half2_rn(v1.x, v1.y);
    dst[64 + 2 * lane + 1] = __floats2half2_rn(v1.z, v1.w);
}

__global__ void ptr_kernel() {
    __shared__ __half tile[32][264];
    int b = blockIdx.x >> 4, n0 = (blockIdx.x & 15) * 32;
    int tid = threadIdx.x, wid = tid >> 5, lane = tid & 31;
#pragma unroll
    for (int s = 0; s < 4; s++) {
        int idx = s * 256 + tid;
        int row = idx >> 5, c = idx & 31;
        *(uint4*)&tile[row][c * 8] =
            *(const uint4*)(g_ph + ((size_t)(b * NN + n0 + row)) * DD + c * 8);
    }
    __syncthreads();
#pragma unroll
    for (int i = 0; i < 32; i++) {
        int d = wid * 32 + i;
        if (lane < 16) {
            __half2 v = __halves2half2(tile[2 * lane][d], tile[2 * lane + 1][d]);
            ((__half2*)(g_pth + ((size_t)(b * DD + d)) * NN + n0))[lane] = v;
        }
    }
}

// ---------------- fused kernel: 512 threads, 4m x 4n warps ----------------
// smem layout (bytes):
#define ESH_B 0                      // 64 x 520 fp16 = 66560
#define XB_B 66560                   // 2 x (64 x 72 fp16) = 2 x 9216
#define PB_B 84992                   // 2 x (256 x 72 fp16) = 2 x 36864
#define PT_B 66560                   // phase 2 alias: 2 x 36864
#define PNS_B 158720                 // 512 f32
#define XNS_B 160768                 // 64 f32
#define INV_B 161024                 // 64 f32
#define RSP_B 161280                 // 256 f32
#define F_SMEM 162304

__global__ __launch_bounds__(512, 1) void cosattn_fused(
    const int* __restrict__ lens, float* __restrict__ wout, float* __restrict__ emb) {
    extern __shared__ char smc[];
    const uint32_t smb = smem_u32(smc);
    __half* Esh = (__half*)(smc + ESH_B);
    float* pns = (float*)(smc + PNS_B);
    float* xns = (float*)(smc + XNS_B);
    float* inv = (float*)(smc + INV_B);
    float* rsp = (float*)(smc + RSP_B);

    int b = blockIdx.x >> 6;
    int l0 = (blockIdx.x & 63) * 64;
    int tid = threadIdx.x;
    int wid = tid >> 5, lane = tid & 31;
    int wm = wid & 3, wn = wid >> 2;          // 4 m-warps x 4 n-warps
    int qg = lane >> 2, qt = lane & 3;

    for (int i = tid; i < NN; i += 512) pns[i] = g_pnorm[b * NN + i];
    if (tid < 64) xns[tid] = g_xnorm[(size_t)b * LL + l0 + tid];
    if (tid < 256) rsp[tid] = 0.f;
    int plen = __ldg(&lens[b]);

    // ---- phase 1: sims, 8 chunks (nch 0..1 x kc 0..3 of 64k) ----
#define ISSUE1(it) do {                                                          \
    int _nch = (it) >> 2, _kc = (it) & 3, _bi = (it) & 1;                        \
    int _k0 = _kc * 64;                                                          \
    const __half* _xs = g_xh + ((size_t)(b * LL + l0)) * DD + _k0;               \
    {                                                                            \
        int row = tid >> 3, c = tid & 7;                                         \
        cp16(smb + XB_B + _bi * 9216 + (row * 72 + c * 8) * 2,                   \
             _xs + (size_t)row * DD + c * 8);                                    \
    }                                                                            \
    const __half* _ps = g_ph + ((size_t)(b * NN + _nch * 256)) * DD + _k0;       \
    _Pragma("unroll")                                                            \
    for (int s = 0; s < 4; s++) {                                                \
        int idx = s * 512 + tid;                                                 \
        int row = idx >> 3, c = idx & 7;                                         \
        cp16(smb + PB_B + _bi * 36864 + (row * 72 + c * 8) * 2,                  \
             _ps + (size_t)row * DD + c * 8);                                    \
    }                                                                            \
    CP_COMMIT();                                                                 \
} while (0)

    float acc[32];
#pragma unroll
    for (int i = 0; i < 32; i++) acc[i] = 0.f;

    ISSUE1(0);
    for (int it = 0; it < 8; ++it) {
        if (it < 7) { ISSUE1(it + 1); CP_WAIT1(); } else { CP_WAIT0(); }
        __syncthreads();
        int bi = it & 1;
        const __half* Xb = (const __half*)(smc + XB_B + bi * 9216);
        const __half* Pb = (const __half*)(smc + PB_B + bi * 36864);
#pragma unroll
        for (int ks = 0; ks < 4; ks++) {
            int kk = ks * 16;
            int r = wm * 16 + qg;
            uint32_t af[4];
            af[0] = *(const uint32_t*)&Xb[r * 72 + kk + 2 * qt];
            af[1] = *(const uint32_t*)&Xb[(r + 8) * 72 + kk + 2 * qt];
            af[2] = *(const uint32_t*)&Xb[r * 72 + kk + 2 * qt + 8];
            af[3] = *(const uint32_t*)&Xb[(r + 8) * 72 + kk + 2 * qt + 8];
#pragma unroll
            for (int nt = 0; nt < 8; nt++) {
                int n = wn * 64 + nt * 8 + qg;
                uint32_t bf[2];
                bf[0] = *(const uint32_t*)&Pb[n * 72 + kk + 2 * qt];
                bf[1] = *(const uint32_t*)&Pb[n * 72 + kk + 2 * qt + 8];
                mma_f16(&acc[nt * 4], af, bf);
            }
        }
        if ((it & 3) == 3) {
            int nch = it >> 2;
            int r0 = wm * 16 + qg;
            float xr0 = xns[r0], xr1 = xns[r0 + 8];
            float sum0 = 0.f, sum1 = 0.f;
#pragma unroll
            for (int nt = 0; nt < 8; nt++) {
                int n = nch * 256 + wn * 64 + nt * 8 + qt * 2;
                float pn0 = pns[n], pn1 = pns[n + 1];
                float* a = &acc[nt * 4];
                float e0 = (n < plen) ? __expf(a[0] / fmaxf(xr0 * pn0, EPSV)) : 0.f;
                float e1 = (n + 1 < plen) ? __expf(a[1] / fmaxf(xr0 * pn1, EPSV)) : 0.f;
                float e2 = (n < plen) ? __expf(a[2] / fmaxf(xr1 * pn0, EPSV)) : 0.f;
                float e3 = (n + 1 < plen) ? __expf(a[3] / fmaxf(xr1 * pn1, EPSV)) : 0.f;
                sum0 += e0 + e1;
                sum1 += e2 + e3;
                *(__half2*)&Esh[r0 * 520 + n] = __floats2half2_rn(e0, e1);
                *(__half2*)&Esh[(r0 + 8) * 520 + n] = __floats2half2_rn(e2, e3);
                a[0] = a[1] = a[2] = a[3] = 0.f;
            }
#pragma unroll
            for (int o = 1; o < 4; o <<= 1) {
                sum0 += __shfl_xor_sync(0xffffffffu, sum0, o);
                sum1 += __shfl_xor_sync(0xffffffffu, sum1, o);
            }
            if (qt == 0) {
                rsp[wn * 64 + r0] += sum0;
                rsp[wn * 64 + r0 + 8] += sum1;
            }
        }
        __syncthreads();
    }

    // ---- transition ----
#define ISSUE2(it) do {                                                          \
    int _bi = (it) & 1;                                                          \
    const __half* _ts = g_pth + (size_t)b * DD * NN + (it) * 64;                 \
    _Pragma("unroll")                                                            \
    for (int s = 0; s < 4; s++) {                                                \
        int idx = s * 512 + tid;                                                 \
        int row = idx >> 3, c = idx & 7;                                         \
        cp16(smb + PT_B + _bi * 36864 + (row * 72 + c * 8) * 2,                  \
             _ts + (size_t)row * NN + c * 8);                                    \
    }                                                                            \
    CP_COMMIT();                                                                 \
} while (0)

    if (tid < 64)
        inv[tid] = 1.0f / (rsp[tid] + rsp[64 + tid] + rsp[128 + tid] + rsp[192 + tid]);
    ISSUE2(0);
    __syncthreads();

    // normalized weights out (overlaps cp.async flight)
    {
        const __half2* Eh2 = (const __half2*)Esh;   // row stride 260 half2
        float* wbase = wout + ((size_t)b * LL + l0) * NN;
#pragma unroll
        for (int s = 0; s < 32; s++) {
            int idx = s * 512 + tid;
            int row = idx >> 8, c2 = idx & 255;
            float2 v = __half22float2(Eh2[row * 260 + c2]);
            float iv = inv[row];
            *(float2*)(wbase + (size_t)row * NN + c2 * 2) = make_float2(v.x * iv, v.y * iv);
        }
    }

    // ---- phase 2: emb = (E @ P) * inv, K=512 over 8 chunks of 64 ----
    for (int it = 0; it < 8; ++it) {
        if (it < 7) { ISSUE2(it + 1); CP_WAIT1(); } else { CP_WAIT0(); }
        __syncthreads();
        int bi = it & 1;
        const __half* Ptb = (const __half*)(smc + PT_B + bi * 36864);
        int nb = it * 64;
#pragma unroll
        for (int ks = 0; ks < 4; ks++) {
            int kk = ks * 16;
            int r = wm * 16 + qg;
            uint32_t af[4];
            af[0] = *(const uint32_t*)&Esh[r * 520 + nb + kk + 2 * qt];
            af[1] = *(const uint32_t*)&Esh[(r + 8) * 520 + nb + kk + 2 * qt];
            af[2] = *(const uint32_t*)&Esh[r * 520 + nb + kk + 2 * qt + 8];
            af[3] = *(const uint32_t*)&Esh[(r + 8) * 520 + nb + kk + 2 * qt + 8];
#pragma unroll
            for (int nt = 0; nt < 8; nt++) {
                int d = wn * 64 + nt * 8 + qg;
                uint32_t bf[2];
                bf[0] = *(const uint32_t*)&Ptb[d * 72 + kk + 2 * qt];
                bf[1] = *(const uint32_t*)&Ptb[d * 72 + kk + 2 * qt + 8];
                mma_f16(&acc[nt * 4], af, bf);
            }
        }
        __syncthreads();
    }

    // epilogue: emb scaled by inv
    {
        int r0 = wm * 16 + qg;
        float iv0 = inv[r0], iv1 = inv[r0 + 8];
#pragma unroll
        for (int nt = 0; nt < 8; nt++) {
            int d = wn * 64 + nt * 8 + qt * 2;
            const float* a = &acc[nt * 4];
            float* e0 = emb + ((size_t)b * LL + l0 + r0) * DD + d;
            float* e1 = emb + ((size_t)b * LL + l0 + r0 + 8) * DD + d;
            *(float2*)e0 = make_float2(a[0] * iv0, a[1] * iv0);
            *(float2*)e1 = make_float2(a[2] * iv1, a[3] * iv1);
        }
    }
}

extern "C" void kernel_launch(void* const* d_in, const int* in_sizes, int n_in,
                              void* d_out, int out_size) {
    const float* x = (const float*)d_in[0];
    const float* prof = (const float*)d_in[1];
    const int* lens = (const int*)d_in[2];
    float* emb = (float*)d_out;
    float* wout = (float*)d_out + (size_t)BB * LL * DD;

    cudaFuncSetAttribute(cosattn_fused, cudaFuncAttributeMaxDynamicSharedMemorySize, F_SMEM);

    cvtx_kernel<<<(BB * LL) / 8, 256>>>(x);
    cvtp_kernel<<<(BB * NN) / 8, 256>>>(prof);
    ptr_kernel<<<BB * (NN / 32), 256>>>();
    cosattn_fused<<<BB * (LL / 64), 512, F_SMEM>>>(lens, wout, emb);
}